// round 10
// baseline (speedup 1.0000x reference)
// UniPhyBlock fused pipeline. Round: revert k2/k4/k5 to scalar R1 (known 750/132/436us),
// keep k3 in f32x2 form (measured 216->118us). End-to-end evidence showed the f32x2
// versions of k2/k4/k5 regressed total by ~600us despite k3's win; reverting isolates
// the verified improvement. Predicted total ~1600-1650us vs best 1719us.
#include <cuda_runtime.h>
#include <math.h>

#define Bc   2
#define Tc   16
#define Dc   64
#define Hc   64
#define Wc   64
#define C2   128
#define Ec   4
#define HIDc 128
#define NSc  0.01f
#define EPSc 1e-5f
#define HWc  4096
#define BTc  32
#define NPIX 131072
#define NBHW 8192
#define PLANE 8388608

typedef unsigned long long ull;

__device__ __forceinline__ ull pack2(float lo, float hi) {
    ull r;
    asm("mov.b64 %0, {%1, %2};" : "=l"(r) : "f"(lo), "f"(hi));
    return r;
}
__device__ __forceinline__ void unpack2(ull v, float& lo, float& hi) {
    asm("mov.b64 {%0, %1}, %2;" : "=f"(lo), "=f"(hi) : "l"(v));
}
#define FMA2(d, a, b, c) asm("fma.rn.f32x2 %0, %1, %2, %3;" : "=l"(d) : "l"(a), "l"(b), "l"(c))

// ---------------- scratch (device globals; no allocation) ----------------
__device__ float g_xc[(size_t)NPIX * C2];
__device__ float g_s1r[PLANE];
__device__ float g_s1i[PLANE];
__device__ float g_ur[PLANE];
__device__ float g_ui[PLANE];
__device__ float g_drift[PLANE];
__device__ float g_ar[BTc * Dc];
__device__ float g_ai[BTc * Dc];
__device__ float g_fr[BTc * Dc];
__device__ float g_fi[BTc * Dc];

// ---------------- K0: per-(b,t,e) decay + forcing tables ----------------
__global__ void k0_tabs(const float* __restrict__ lam_re,
                        const float* __restrict__ lam_im,
                        const float* __restrict__ dt) {
    int idx = blockIdx.x * blockDim.x + threadIdx.x;
    if (idx >= BTc * Dc) return;
    int bt = idx / Dc, e = idx % Dc;
    float lr = lam_re[e];
    float sp = lr > 0.f ? lr + log1pf(expf(-lr)) : log1pf(expf(lr));
    float lre = -sp, lim = lam_im[e];
    float dtv = dt[bt];
    float er = expf(lre * dtv);
    float s, c;
    sincosf(lim * dtv, &s, &c);
    float ar = er * c, ai = er * s;
    float nr = ar - 1.f, ni = ai;
    float den = lre * lre + lim * lim;
    g_ar[idx] = ar; g_ai[idx] = ai;
    g_fr[idx] = (nr * lre + ni * lim) / den;
    g_fi[idx] = (ni * lre - nr * lim) / den;
}

// ---------------- K1: spatial complex LayerNorm -> NHWC concat ----------------
__global__ void __launch_bounds__(256) k1_ln_spatial(
        const float* __restrict__ xr, const float* __restrict__ xi,
        const float* __restrict__ lw, const float* __restrict__ lb) {
    __shared__ float sre[Dc][33], sim[Dc][33];
    __shared__ float smu[32], srs[32];
    int blk = blockIdx.x;
    int wt = blk & 1, h = (blk >> 1) & 63, bt = blk >> 7;
    int w0 = wt * 32;
    int tid = threadIdx.x;
    size_t base = ((size_t)bt * Dc) * HWc + h * Wc + w0;
    for (int lin = tid; lin < Dc * 32; lin += 256) {
        int d = lin >> 5, w = lin & 31;
        sre[d][w] = xr[base + (size_t)d * HWc + w];
        sim[d][w] = xi[base + (size_t)d * HWc + w];
    }
    __syncthreads();
    if (tid < 32) {
        float s = 0.f, sq = 0.f;
        for (int d = 0; d < Dc; d++) {
            float a = sre[d][tid], b = sim[d][tid];
            s += a + b; sq += a * a + b * b;
        }
        float mu = s * (1.f / 128.f);
        float var = sq * (1.f / 128.f) - mu * mu;
        smu[tid] = mu;
        srs[tid] = rsqrtf(var + EPSc);
    }
    __syncthreads();
    size_t obase = ((size_t)(bt * Hc + h) * Wc + w0) * C2;
    for (int lin = tid; lin < C2 * 32; lin += 256) {
        int w = lin >> 7, c = lin & 127;
        float v = (c < Dc) ? sre[c][w] : sim[c - Dc][w];
        v = (v - smu[w]) * srs[w] * lw[c] + lb[c];
        g_xc[obase + (size_t)w * C2 + c] = v;
    }
}

// ---------------- K2: 3x3 conv 128->128 + bias + resid (scalar, R1) ----------------
__global__ void __launch_bounds__(128) k2_conv(
        const float* __restrict__ cw, const float* __restrict__ cb,
        const float* __restrict__ xr, const float* __restrict__ xi) {
    __shared__ float sRow[34 * C2];
    int blk = blockIdx.x;
    int wt = blk & 1, h = (blk >> 1) & 63, bt = blk >> 7;
    int w0 = wt * 32;
    int o = threadIdx.x;
    float acc[32];
    float bias = cb[o];
#pragma unroll
    for (int p = 0; p < 32; p++) acc[p] = bias;

    for (int ky = 0; ky < 3; ky++) {
        int hh = h - 1 + ky;
        __syncthreads();
        for (int q = 0; q < 34; q++) {
            int ww = w0 - 1 + q;
            float v = 0.f;
            if (hh >= 0 && hh < Hc && ww >= 0 && ww < Wc)
                v = g_xc[((size_t)bt * HWc + hh * Wc + ww) * C2 + o];
            sRow[q * C2 + o] = v;
        }
        __syncthreads();
        const float* wbase = cw + (size_t)(ky * 3) * C2 * C2 + o;
        for (int ci = 0; ci < C2; ci++) {
            float wA = wbase[ci * C2];
            float wB = wbase[C2 * C2 + ci * C2];
            float wC = wbase[2 * C2 * C2 + ci * C2];
            float v[34];
#pragma unroll
            for (int q = 0; q < 34; q++) v[q] = sRow[q * C2 + ci];
#pragma unroll
            for (int p = 0; p < 32; p++)
                acc[p] += v[p] * wA + v[p + 1] * wB + v[p + 2] * wC;
        }
    }
    __syncthreads();
#pragma unroll
    for (int p = 0; p < 32; p++) sRow[o * 33 + p] = acc[p];
    __syncthreads();
    size_t pbase = ((size_t)bt * Dc) * HWc + h * Wc + w0;
    for (int lin = threadIdx.x; lin < C2 * 32; lin += 128) {
        int c = lin >> 5, p = lin & 31;
        float y = sRow[c * 33 + p];
        size_t addr = pbase + (size_t)(c & 63) * HWc + p;
        if (c < Dc) g_s1r[addr] = y + xr[addr];
        else        g_s1i[addr] = y + xi[addr];
    }
}

// ---------------- K3: temporal complex LN + encode (f32x2, measured fast) ----------------
__global__ void __launch_bounds__(256) k3_lnt_enc(
        const float* __restrict__ lw, const float* __restrict__ lb,
        const float* __restrict__ er, const float* __restrict__ ei,
        const float* __restrict__ sbr, const float* __restrict__ sbi,
        const float* __restrict__ dt,
        const float* __restrict__ nzr, const float* __restrict__ nzi) {
    __shared__ __align__(16) float sre[Dc][36], sim[Dc][36];
    __shared__ float smu[32], srs[32];
    int blk = blockIdx.x;
    int wt = blk & 1, h = (blk >> 1) & 63, t = (blk >> 7) & 15, b = blk >> 11;
    int w0 = wt * 32;
    int tid = threadIdx.x;
    int bt = b * Tc + t;
    size_t base = ((size_t)bt * Dc) * HWc + h * Wc + w0;
    for (int lin = tid; lin < Dc * 32; lin += 256) {
        int d = lin >> 5, w = lin & 31;
        sre[d][w] = g_s1r[base + (size_t)d * HWc + w];
        sim[d][w] = g_s1i[base + (size_t)d * HWc + w];
    }
    __syncthreads();
    if (tid < 32) {
        float s = 0.f, sq = 0.f;
        for (int d = 0; d < Dc; d++) {
            float a = sre[d][tid], b2 = sim[d][tid];
            s += a + b2; sq += a * a + b2 * b2;
        }
        float mu = s * (1.f / 128.f);
        float var = sq * (1.f / 128.f) - mu * mu;
        smu[tid] = mu;
        srs[tid] = rsqrtf(var + EPSc);
    }
    __syncthreads();
    for (int lin = tid; lin < Dc * 32; lin += 256) {
        int d = lin >> 5, w = lin & 31;
        float m = smu[w], rs = srs[w];
        sre[d][w] = (sre[d][w] - m) * rs * lw[d] + lb[d];
        sim[d][w] = (sim[d][w] - m) * rs * lw[d + Dc] + lb[d + Dc];
    }
    __syncthreads();
    int e = tid & 63, g = tid >> 6;
    ull aR[4], aI[4];
#pragma unroll
    for (int k = 0; k < 4; k++) { aR[k] = 0ULL; aI[k] = 0ULL; }
    for (int d = 0; d < Dc; d++) {
        float eR = er[d * Dc + e], eI = ei[d * Dc + e];
        ull pR = pack2(eR, eR), pI = pack2(eI, eI), nI = pack2(-eI, -eI);
        const ull* xR = reinterpret_cast<const ull*>(&sre[d][g * 8]);
        const ull* xI = reinterpret_cast<const ull*>(&sim[d][g * 8]);
#pragma unroll
        for (int k = 0; k < 4; k++) {
            FMA2(aR[k], xR[k], pR, aR[k]);
            FMA2(aR[k], xI[k], nI, aR[k]);
            FMA2(aI[k], xR[k], pI, aI[k]);
            FMA2(aI[k], xI[k], pR, aI[k]);
        }
    }
    float dtv = dt[bt];
    float sq_dt = sqrtf(dtv) * NSc;
    float fR = g_fr[bt * Dc + e], fI = g_fi[bt * Dc + e];
    float bR = sbr[e], bI = sbi[e];
#pragma unroll
    for (int k = 0; k < 8; k++) {
        float aRk, aIk, tmp;
        if (k & 1) { unpack2(aR[k >> 1], tmp, aRk); unpack2(aI[k >> 1], tmp, aIk); }
        else       { unpack2(aR[k >> 1], aRk, tmp); unpack2(aI[k >> 1], aIk, tmp); }
        int w = g * 8 + k;
        size_t n = (size_t)b * HWc + h * Wc + w0 + w;
        size_t off = (n * Tc + t) * Dc + e;
        float uR = aRk + bR, uI = aIk + bI;
        float vR = uR * fR - uI * fI;
        float vI = uR * fI + uI * fR;
        vR += sq_dt * nzr[off];
        vI += sq_dt * nzi[off];
        g_ur[off] = vR;
        g_ui[off] = vI;
    }
}

// ---------------- K4: recurrence scan over T + decode (scalar, R1) ----------------
__global__ void __launch_bounds__(256) k4_scan_dec(
        const float* __restrict__ dr_, const float* __restrict__ di_) {
    __shared__ float shR[4][16][64], shI[4][16][64];
    int blk = blockIdx.x;
    int n0 = blk * 4;
    int tid = threadIdx.x;
    int nn = tid >> 6, e = tid & 63;
    int n = n0 + nn;
    int b = n / HWc;
    float hR = 0.f, hI = 0.f;
    size_t ub = ((size_t)n * Tc) * Dc + e;
    for (int t = 0; t < Tc; t++) {
        int ti = (b * Tc + t) * Dc + e;
        float aRv = g_ar[ti], aIv = g_ai[ti];
        float uR = g_ur[ub + t * Dc], uI = g_ui[ub + t * Dc];
        float nR = aRv * hR - aIv * hI + uR;
        float nI = aRv * hI + aIv * hR + uI;
        hR = nR; hI = nI;
        shR[nn][t][e] = hR;
        shI[nn][t][e] = hI;
    }
    __syncthreads();
    int d = tid & 63, grp = tid >> 6;
    float acc[16];
#pragma unroll
    for (int t = 0; t < 16; t++) acc[t] = 0.f;
    for (int ee = 0; ee < Dc; ee++) {
        float DR = dr_[ee * Dc + d], DI = di_[ee * Dc + d];
#pragma unroll
        for (int t = 0; t < 16; t++)
            acc[t] += shR[grp][t][ee] * DR - shI[grp][t][ee] * DI;
    }
    size_t ob = ((size_t)(n0 + grp) * Tc) * Dc + d;
#pragma unroll
    for (int t = 0; t < 16; t++) g_drift[ob + t * Dc] = acc[t];
}

// ---------------- K5: MoE FFN (dense over 4 experts, scalar, R1) ----------------
__global__ void __launch_bounds__(256) k5_moe(
        const float* __restrict__ rw, const float* __restrict__ rb,
        const float* __restrict__ w1, const float* __restrict__ b1,
        const float* __restrict__ w2, const float* __restrict__ b2,
        float* __restrict__ out) {
    __shared__ float tokS[C2][33];
    __shared__ float hdnS[C2][33];
    __shared__ float gS[32][5];
    int blk = blockIdx.x;
    int wt = blk & 1, h = (blk >> 1) & 63, t = (blk >> 7) & 15, b = blk >> 11;
    int w0 = wt * 32;
    int tid = threadIdx.x;
    int bt = b * Tc + t;
    size_t base = ((size_t)bt * Dc) * HWc + h * Wc + w0;
    size_t nb = (size_t)b * HWc + h * Wc + w0;
    for (int lin = tid; lin < Dc * 32; lin += 256) {
        int w = lin >> 6, d = lin & 63;
        tokS[d][w] = g_drift[((nb + w) * Tc + t) * Dc + d];
    }
    __syncthreads();
    for (int lin = tid; lin < Dc * 32; lin += 256) {
        int d = lin >> 5, w = lin & 31;
        tokS[d][w] += g_s1r[base + (size_t)d * HWc + w];
        tokS[d + Dc][w] = g_s1i[base + (size_t)d * HWc + w];
    }
    __syncthreads();
    if (tid < 128) {
        int w = tid >> 2, e = tid & 3;
        float s = rb[e];
        for (int c = 0; c < C2; c++) s += tokS[c][w] * rw[c * Ec + e];
        gS[w][e] = s;
    }
    __syncthreads();
    if (tid < 32) {
        float m = fmaxf(fmaxf(gS[tid][0], gS[tid][1]), fmaxf(gS[tid][2], gS[tid][3]));
        float e0 = expf(gS[tid][0] - m), e1 = expf(gS[tid][1] - m);
        float e2 = expf(gS[tid][2] - m), e3 = expf(gS[tid][3] - m);
        float inv = 1.f / (e0 + e1 + e2 + e3);
        gS[tid][0] = e0 * inv; gS[tid][1] = e1 * inv;
        gS[tid][2] = e2 * inv; gS[tid][3] = e3 * inv;
    }
    __syncthreads();
    int col = tid & 127, hf = tid >> 7;
    float outA[16];
#pragma unroll
    for (int k = 0; k < 16; k++) outA[k] = 0.f;
    for (int ex = 0; ex < Ec; ex++) {
        float acc[16];
        float bb = b1[ex * HIDc + col];
#pragma unroll
        for (int k = 0; k < 16; k++) acc[k] = bb;
        const float* w1p = w1 + (size_t)ex * C2 * HIDc + col;
        for (int d = 0; d < C2; d++) {
            float wv = w1p[d * HIDc];
#pragma unroll
            for (int k = 0; k < 16; k++) acc[k] += tokS[d][hf * 16 + k] * wv;
        }
#pragma unroll
        for (int k = 0; k < 16; k++) {
            float x = acc[k];
            acc[k] = 0.5f * x * (1.f + tanhf(0.7978845608028654f * (x + 0.044715f * x * x * x)));
        }
        __syncthreads();
#pragma unroll
        for (int k = 0; k < 16; k++) hdnS[col][hf * 16 + k] = acc[k];
        __syncthreads();
        float acc2[16];
        float b2v = b2[ex * C2 + col];
#pragma unroll
        for (int k = 0; k < 16; k++) acc2[k] = b2v;
        const float* w2p = w2 + (size_t)ex * HIDc * C2 + col;
        for (int hh = 0; hh < HIDc; hh++) {
            float wv = w2p[hh * C2];
#pragma unroll
            for (int k = 0; k < 16; k++) acc2[k] += hdnS[hh][hf * 16 + k] * wv;
        }
#pragma unroll
        for (int k = 0; k < 16; k++) outA[k] += gS[hf * 16 + k][ex] * acc2[k];
    }
    __syncthreads();
#pragma unroll
    for (int k = 0; k < 16; k++) hdnS[col][hf * 16 + k] = outA[k];
    __syncthreads();
    for (int lin = tid; lin < C2 * 32; lin += 256) {
        int c = lin >> 5, p = lin & 31;
        float val = tokS[c][p] + hdnS[c][p];
        size_t addr = base + (size_t)(c & 63) * HWc + p;
        if (c >= Dc) addr += (size_t)PLANE;
        out[addr] = val;
    }
}

// ---------------- launch ----------------
extern "C" void kernel_launch(void* const* d_in, const int* in_sizes, int n_in,
                              void* d_out, int out_size) {
    (void)in_sizes; (void)n_in; (void)out_size;
    const float* x_real = (const float*)d_in[0];
    const float* x_imag = (const float*)d_in[1];
    const float* dt     = (const float*)d_in[2];
    const float* nzr    = (const float*)d_in[3];
    const float* nzi    = (const float*)d_in[4];
    const float* ln_s_w = (const float*)d_in[5];
    const float* ln_s_b = (const float*)d_in[6];
    const float* conv_w = (const float*)d_in[7];
    const float* conv_b = (const float*)d_in[8];
    const float* ln_t_w = (const float*)d_in[9];
    const float* ln_t_b = (const float*)d_in[10];
    const float* lam_re = (const float*)d_in[11];
    const float* lam_im = (const float*)d_in[12];
    const float* sbr    = (const float*)d_in[13];
    const float* sbi    = (const float*)d_in[14];
    const float* enc_re = (const float*)d_in[15];
    const float* enc_im = (const float*)d_in[16];
    const float* dec_re = (const float*)d_in[17];
    const float* dec_im = (const float*)d_in[18];
    const float* rw     = (const float*)d_in[19];
    const float* rb     = (const float*)d_in[20];
    const float* w1     = (const float*)d_in[21];
    const float* b1     = (const float*)d_in[22];
    const float* w2     = (const float*)d_in[23];
    const float* b2     = (const float*)d_in[24];
    float* out = (float*)d_out;

    k0_tabs<<<8, 256>>>(lam_re, lam_im, dt);
    k1_ln_spatial<<<4096, 256>>>(x_real, x_imag, ln_s_w, ln_s_b);
    k2_conv<<<4096, 128>>>(conv_w, conv_b, x_real, x_imag);
    k3_lnt_enc<<<4096, 256>>>(ln_t_w, ln_t_b, enc_re, enc_im, sbr, sbi, dt, nzr, nzi);
    k4_scan_dec<<<2048, 256>>>(dec_re, dec_im);
    k5_moe<<<4096, 256>>>(rw, rb, w1, b1, w2, b2, out);
}

// round 11
// speedup vs baseline: 1.3182x; 1.3182x over previous
// UniPhyBlock fused pipeline. Round: restore R6 champion (f32x2 everywhere;
// best measured 2284us in current env vs 3258 scalar) + widen k2 to 64px/block:
// halves per-pixel weight L2 traffic, halves halo overhead, and chunked pixel
// windows (v2[10]) keep regs ~110 (R6's k2 spilled with acc[32]+v2[34] ull).
#include <cuda_runtime.h>
#include <math.h>

#define Bc   2
#define Tc   16
#define Dc   64
#define Hc   64
#define Wc   64
#define C2   128
#define Ec   4
#define HIDc 128
#define NSc  0.01f
#define EPSc 1e-5f
#define HWc  4096
#define BTc  32
#define NPIX 131072
#define NBHW 8192
#define PLANE 8388608

typedef unsigned long long ull;

__device__ __forceinline__ ull pack2(float lo, float hi) {
    ull r;
    asm("mov.b64 %0, {%1, %2};" : "=l"(r) : "f"(lo), "f"(hi));
    return r;
}
__device__ __forceinline__ void unpack2(ull v, float& lo, float& hi) {
    asm("mov.b64 {%0, %1}, %2;" : "=f"(lo), "=f"(hi) : "l"(v));
}
#define FMA2(d, a, b, c) asm("fma.rn.f32x2 %0, %1, %2, %3;" : "=l"(d) : "l"(a), "l"(b), "l"(c))

// ---------------- scratch (device globals; no allocation) ----------------
__device__ float g_xc[(size_t)NPIX * C2];
__device__ float g_s1r[PLANE];
__device__ float g_s1i[PLANE];
__device__ float g_ur[PLANE];
__device__ float g_ui[PLANE];
__device__ float g_drift[PLANE];
__device__ float g_ar[BTc * Dc];
__device__ float g_ai[BTc * Dc];
__device__ float g_fr[BTc * Dc];
__device__ float g_fi[BTc * Dc];

// ---------------- K0: per-(b,t,e) decay + forcing tables ----------------
__global__ void k0_tabs(const float* __restrict__ lam_re,
                        const float* __restrict__ lam_im,
                        const float* __restrict__ dt) {
    int idx = blockIdx.x * blockDim.x + threadIdx.x;
    if (idx >= BTc * Dc) return;
    int bt = idx / Dc, e = idx % Dc;
    float lr = lam_re[e];
    float sp = lr > 0.f ? lr + log1pf(expf(-lr)) : log1pf(expf(lr));
    float lre = -sp, lim = lam_im[e];
    float dtv = dt[bt];
    float er = expf(lre * dtv);
    float s, c;
    sincosf(lim * dtv, &s, &c);
    float ar = er * c, ai = er * s;
    float nr = ar - 1.f, ni = ai;
    float den = lre * lre + lim * lim;
    g_ar[idx] = ar; g_ai[idx] = ai;
    g_fr[idx] = (nr * lre + ni * lim) / den;
    g_fi[idx] = (ni * lre - nr * lim) / den;
}

// ---------------- K1: spatial complex LayerNorm -> NHWC concat ----------------
__global__ void __launch_bounds__(256) k1_ln_spatial(
        const float* __restrict__ xr, const float* __restrict__ xi,
        const float* __restrict__ lw, const float* __restrict__ lb) {
    __shared__ float sre[Dc][33], sim[Dc][33];
    __shared__ float smu[32], srs[32];
    int blk = blockIdx.x;
    int wt = blk & 1, h = (blk >> 1) & 63, bt = blk >> 7;
    int w0 = wt * 32;
    int tid = threadIdx.x;
    size_t base = ((size_t)bt * Dc) * HWc + h * Wc + w0;
    for (int lin = tid; lin < Dc * 32; lin += 256) {
        int d = lin >> 5, w = lin & 31;
        sre[d][w] = xr[base + (size_t)d * HWc + w];
        sim[d][w] = xi[base + (size_t)d * HWc + w];
    }
    __syncthreads();
    if (tid < 32) {
        float s = 0.f, sq = 0.f;
        for (int d = 0; d < Dc; d++) {
            float a = sre[d][tid], b = sim[d][tid];
            s += a + b; sq += a * a + b * b;
        }
        float mu = s * (1.f / 128.f);
        float var = sq * (1.f / 128.f) - mu * mu;
        smu[tid] = mu;
        srs[tid] = rsqrtf(var + EPSc);
    }
    __syncthreads();
    size_t obase = ((size_t)(bt * Hc + h) * Wc + w0) * C2;
    for (int lin = tid; lin < C2 * 32; lin += 256) {
        int w = lin >> 7, c = lin & 127;
        float v = (c < Dc) ? sre[c][w] : sim[c - Dc][w];
        v = (v - smu[w]) * srs[w] * lw[c] + lb[c];
        g_xc[obase + (size_t)w * C2 + c] = v;
    }
}

// ---------------- K2: 3x3 conv 128->128 + bias + resid ----------------
// 64 pixels/block (full W row), 256 thr = 128 out-ch x 2 pixel halves (32 px
// each). f32x2 over input-channel pairs; chunked 8-px windows keep regs ~110.
__global__ void __launch_bounds__(256) k2_conv(
        const float* __restrict__ cw, const float* __restrict__ cb,
        const float* __restrict__ xr, const float* __restrict__ xi) {
    __shared__ __align__(16) float sRow[66 * C2];   // 33792 B
    int blk = blockIdx.x;              // 2048 = bt*64 + h
    int h = blk & 63, bt = blk >> 6;
    int tid = threadIdx.x;
    int o = tid & 127, ph = tid >> 7;
    int p0 = ph * 32;
    ull acc[32];
    float bias = cb[o];
#pragma unroll
    for (int p = 0; p < 32; p++) acc[p] = pack2(bias, 0.f);

    for (int ky = 0; ky < 3; ky++) {
        int hh = h - 1 + ky;
        __syncthreads();
        for (int lin = tid; lin < 66 * C2; lin += 256) {
            int q = lin >> 7, c = lin & 127;   // q 0..65 -> ww = q-1
            int ww = q - 1;
            float v = 0.f;
            if (hh >= 0 && hh < Hc && ww >= 0 && ww < Wc)
                v = g_xc[((size_t)bt * HWc + hh * Wc + ww) * C2 + c];
            sRow[q * C2 + c] = v;
        }
        __syncthreads();
        const float* wbase = cw + (size_t)(ky * 3) * C2 * C2 + o;
        for (int ci = 0; ci < C2; ci += 2) {
            ull wA = pack2(wbase[ci * C2],               wbase[(ci + 1) * C2]);
            ull wB = pack2(wbase[C2 * C2 + ci * C2],     wbase[C2 * C2 + (ci + 1) * C2]);
            ull wC = pack2(wbase[2 * C2 * C2 + ci * C2], wbase[2 * C2 * C2 + (ci + 1) * C2]);
#pragma unroll
            for (int c4 = 0; c4 < 4; c4++) {
                ull v2[10];
#pragma unroll
                for (int j = 0; j < 10; j++)
                    v2[j] = *reinterpret_cast<const ull*>(&sRow[(p0 + c4 * 8 + j) * C2 + ci]);
#pragma unroll
                for (int k = 0; k < 8; k++) {
                    int p = c4 * 8 + k;
                    FMA2(acc[p], v2[k],     wA, acc[p]);
                    FMA2(acc[p], v2[k + 1], wB, acc[p]);
                    FMA2(acc[p], v2[k + 2], wC, acc[p]);
                }
            }
        }
    }
    __syncthreads();
    // reduce lanes + transpose through smem (128*65 = 8320 <= 8448 floats)
#pragma unroll
    for (int p = 0; p < 32; p++) {
        float lo, hi; unpack2(acc[p], lo, hi);
        sRow[o * 65 + p0 + p] = lo + hi;
    }
    __syncthreads();
    size_t pbase = ((size_t)bt * Dc) * HWc + h * Wc;
    for (int lin = tid; lin < C2 * 64; lin += 256) {
        int c = lin >> 6, p = lin & 63;
        float y = sRow[c * 65 + p];
        size_t addr = pbase + (size_t)(c & 63) * HWc + p;
        if (c < Dc) g_s1r[addr] = y + xr[addr];
        else        g_s1i[addr] = y + xi[addr];
    }
}

// ---------------- K3: temporal complex LN + encode (f32x2) ----------------
__global__ void __launch_bounds__(256) k3_lnt_enc(
        const float* __restrict__ lw, const float* __restrict__ lb,
        const float* __restrict__ er, const float* __restrict__ ei,
        const float* __restrict__ sbr, const float* __restrict__ sbi,
        const float* __restrict__ dt,
        const float* __restrict__ nzr, const float* __restrict__ nzi) {
    __shared__ __align__(16) float sre[Dc][36], sim[Dc][36];
    __shared__ float smu[32], srs[32];
    int blk = blockIdx.x;
    int wt = blk & 1, h = (blk >> 1) & 63, t = (blk >> 7) & 15, b = blk >> 11;
    int w0 = wt * 32;
    int tid = threadIdx.x;
    int bt = b * Tc + t;
    size_t base = ((size_t)bt * Dc) * HWc + h * Wc + w0;
    for (int lin = tid; lin < Dc * 32; lin += 256) {
        int d = lin >> 5, w = lin & 31;
        sre[d][w] = g_s1r[base + (size_t)d * HWc + w];
        sim[d][w] = g_s1i[base + (size_t)d * HWc + w];
    }
    __syncthreads();
    if (tid < 32) {
        float s = 0.f, sq = 0.f;
        for (int d = 0; d < Dc; d++) {
            float a = sre[d][tid], b2 = sim[d][tid];
            s += a + b2; sq += a * a + b2 * b2;
        }
        float mu = s * (1.f / 128.f);
        float var = sq * (1.f / 128.f) - mu * mu;
        smu[tid] = mu;
        srs[tid] = rsqrtf(var + EPSc);
    }
    __syncthreads();
    for (int lin = tid; lin < Dc * 32; lin += 256) {
        int d = lin >> 5, w = lin & 31;
        float m = smu[w], rs = srs[w];
        sre[d][w] = (sre[d][w] - m) * rs * lw[d] + lb[d];
        sim[d][w] = (sim[d][w] - m) * rs * lw[d + Dc] + lb[d + Dc];
    }
    __syncthreads();
    int e = tid & 63, g = tid >> 6;
    ull aR[4], aI[4];
#pragma unroll
    for (int k = 0; k < 4; k++) { aR[k] = 0ULL; aI[k] = 0ULL; }
    for (int d = 0; d < Dc; d++) {
        float eR = er[d * Dc + e], eI = ei[d * Dc + e];
        ull pR = pack2(eR, eR), pI = pack2(eI, eI), nI = pack2(-eI, -eI);
        const ull* xR = reinterpret_cast<const ull*>(&sre[d][g * 8]);
        const ull* xI = reinterpret_cast<const ull*>(&sim[d][g * 8]);
#pragma unroll
        for (int k = 0; k < 4; k++) {
            FMA2(aR[k], xR[k], pR, aR[k]);
            FMA2(aR[k], xI[k], nI, aR[k]);
            FMA2(aI[k], xR[k], pI, aI[k]);
            FMA2(aI[k], xI[k], pR, aI[k]);
        }
    }
    float dtv = dt[bt];
    float sq_dt = sqrtf(dtv) * NSc;
    float fR = g_fr[bt * Dc + e], fI = g_fi[bt * Dc + e];
    float bR = sbr[e], bI = sbi[e];
#pragma unroll
    for (int k = 0; k < 8; k++) {
        float aRk, aIk, tmp;
        if (k & 1) { unpack2(aR[k >> 1], tmp, aRk); unpack2(aI[k >> 1], tmp, aIk); }
        else       { unpack2(aR[k >> 1], aRk, tmp); unpack2(aI[k >> 1], aIk, tmp); }
        int w = g * 8 + k;
        size_t n = (size_t)b * HWc + h * Wc + w0 + w;
        size_t off = (n * Tc + t) * Dc + e;
        float uR = aRk + bR, uI = aIk + bI;
        float vR = uR * fR - uI * fI;
        float vI = uR * fI + uI * fR;
        vR += sq_dt * nzr[off];
        vI += sq_dt * nzi[off];
        g_ur[off] = vR;
        g_ui[off] = vI;
    }
}

// ---------------- K4: recurrence scan over T + decode (f32x2, ee-pairs) ----------------
__global__ void __launch_bounds__(256) k4_scan_dec(
        const float* __restrict__ dr_, const float* __restrict__ di_) {
    __shared__ __align__(16) float shR[4][16][64], shI[4][16][64];
    int blk = blockIdx.x;
    int n0 = blk * 4;
    int tid = threadIdx.x;
    int nn = tid >> 6, e = tid & 63;
    int n = n0 + nn;
    int b = n / HWc;
    float hR = 0.f, hI = 0.f;
    size_t ub = ((size_t)n * Tc) * Dc + e;
    for (int t = 0; t < Tc; t++) {
        int ti = (b * Tc + t) * Dc + e;
        float aRv = g_ar[ti], aIv = g_ai[ti];
        float uR = g_ur[ub + t * Dc], uI = g_ui[ub + t * Dc];
        float nR = aRv * hR - aIv * hI + uR;
        float nI = aRv * hI + aIv * hR + uI;
        hR = nR; hI = nI;
        shR[nn][t][e] = hR;
        shI[nn][t][e] = hI;
    }
    __syncthreads();
    int d = tid & 63, grp = tid >> 6;
    ull acc2[16];
#pragma unroll
    for (int t = 0; t < 16; t++) acc2[t] = 0ULL;
    for (int ee = 0; ee < Dc; ee += 2) {
        ull pR  = pack2(dr_[ee * Dc + d],  dr_[(ee + 1) * Dc + d]);
        ull pnI = pack2(-di_[ee * Dc + d], -di_[(ee + 1) * Dc + d]);
#pragma unroll
        for (int t = 0; t < 16; t++) {
            ull hr = *reinterpret_cast<const ull*>(&shR[grp][t][ee]);
            ull hi = *reinterpret_cast<const ull*>(&shI[grp][t][ee]);
            FMA2(acc2[t], hr, pR,  acc2[t]);
            FMA2(acc2[t], hi, pnI, acc2[t]);
        }
    }
    size_t ob = ((size_t)(n0 + grp) * Tc) * Dc + d;
#pragma unroll
    for (int t = 0; t < 16; t++) {
        float lo, hi; unpack2(acc2[t], lo, hi);
        g_drift[ob + t * Dc] = lo + hi;
    }
}

// ---------------- K5: MoE FFN (dense, f32x2 pixel-pairs) ----------------
__global__ void __launch_bounds__(256) k5_moe(
        const float* __restrict__ rw, const float* __restrict__ rb,
        const float* __restrict__ w1, const float* __restrict__ b1,
        const float* __restrict__ w2, const float* __restrict__ b2,
        float* __restrict__ out) {
    __shared__ __align__(16) float tokS[C2][36];
    __shared__ __align__(16) float hdnS[C2][36];
    __shared__ float gS[32][5];
    int blk = blockIdx.x;
    int wt = blk & 1, h = (blk >> 1) & 63, t = (blk >> 7) & 15, b = blk >> 11;
    int w0 = wt * 32;
    int tid = threadIdx.x;
    int bt = b * Tc + t;
    size_t base = ((size_t)bt * Dc) * HWc + h * Wc + w0;
    size_t nb = (size_t)b * HWc + h * Wc + w0;
    for (int lin = tid; lin < Dc * 32; lin += 256) {
        int w = lin >> 6, d = lin & 63;
        tokS[d][w] = g_drift[((nb + w) * Tc + t) * Dc + d];
    }
    __syncthreads();
    for (int lin = tid; lin < Dc * 32; lin += 256) {
        int d = lin >> 5, w = lin & 31;
        tokS[d][w] += g_s1r[base + (size_t)d * HWc + w];
        tokS[d + Dc][w] = g_s1i[base + (size_t)d * HWc + w];
    }
    __syncthreads();
    if (tid < 128) {
        int w = tid >> 2, e = tid & 3;
        float s = rb[e];
        for (int c = 0; c < C2; c++) s += tokS[c][w] * rw[c * Ec + e];
        gS[w][e] = s;
    }
    __syncthreads();
    if (tid < 32) {
        float m = fmaxf(fmaxf(gS[tid][0], gS[tid][1]), fmaxf(gS[tid][2], gS[tid][3]));
        float e0 = expf(gS[tid][0] - m), e1 = expf(gS[tid][1] - m);
        float e2 = expf(gS[tid][2] - m), e3 = expf(gS[tid][3] - m);
        float inv = 1.f / (e0 + e1 + e2 + e3);
        gS[tid][0] = e0 * inv; gS[tid][1] = e1 * inv;
        gS[tid][2] = e2 * inv; gS[tid][3] = e3 * inv;
    }
    __syncthreads();
    int col = tid & 127, hf = tid >> 7;
    ull outA[8];
#pragma unroll
    for (int k = 0; k < 8; k++) outA[k] = 0ULL;
    for (int ex = 0; ex < Ec; ex++) {
        ull acc[8];
        float bb = b1[ex * HIDc + col];
        ull bb2 = pack2(bb, bb);
#pragma unroll
        for (int k = 0; k < 8; k++) acc[k] = bb2;
        const float* w1p = w1 + (size_t)ex * C2 * HIDc + col;
        for (int d = 0; d < C2; d++) {
            float wv = w1p[d * HIDc];
            ull wp = pack2(wv, wv);
            const ull* vp = reinterpret_cast<const ull*>(&tokS[d][hf * 16]);
#pragma unroll
            for (int k = 0; k < 8; k++) FMA2(acc[k], vp[k], wp, acc[k]);
        }
        __syncthreads();
#pragma unroll
        for (int k = 0; k < 8; k++) {
            float x0, x1; unpack2(acc[k], x0, x1);
            x0 = 0.5f * x0 * (1.f + tanhf(0.7978845608028654f * (x0 + 0.044715f * x0 * x0 * x0)));
            x1 = 0.5f * x1 * (1.f + tanhf(0.7978845608028654f * (x1 + 0.044715f * x1 * x1 * x1)));
            hdnS[col][hf * 16 + 2 * k]     = x0;
            hdnS[col][hf * 16 + 2 * k + 1] = x1;
        }
        __syncthreads();
        ull acc2[8];
        float b2v = b2[ex * C2 + col];
        ull b2p = pack2(b2v, b2v);
#pragma unroll
        for (int k = 0; k < 8; k++) acc2[k] = b2p;
        const float* w2p = w2 + (size_t)ex * HIDc * C2 + col;
        for (int hh = 0; hh < HIDc; hh++) {
            float wv = w2p[hh * C2];
            ull wp = pack2(wv, wv);
            const ull* vp = reinterpret_cast<const ull*>(&hdnS[hh][hf * 16]);
#pragma unroll
            for (int k = 0; k < 8; k++) FMA2(acc2[k], vp[k], wp, acc2[k]);
        }
#pragma unroll
        for (int k = 0; k < 8; k++) {
            ull gp = pack2(gS[hf * 16 + 2 * k][ex], gS[hf * 16 + 2 * k + 1][ex]);
            FMA2(outA[k], acc2[k], gp, outA[k]);
        }
    }
    __syncthreads();
#pragma unroll
    for (int k = 0; k < 8; k++) {
        float lo, hi; unpack2(outA[k], lo, hi);
        hdnS[col][hf * 16 + 2 * k]     = lo;
        hdnS[col][hf * 16 + 2 * k + 1] = hi;
    }
    __syncthreads();
    for (int lin = tid; lin < C2 * 32; lin += 256) {
        int c = lin >> 5, p = lin & 31;
        float val = tokS[c][p] + hdnS[c][p];
        size_t addr = base + (size_t)(c & 63) * HWc + p;
        if (c >= Dc) addr += (size_t)PLANE;
        out[addr] = val;
    }
}

// ---------------- launch ----------------
extern "C" void kernel_launch(void* const* d_in, const int* in_sizes, int n_in,
                              void* d_out, int out_size) {
    (void)in_sizes; (void)n_in; (void)out_size;
    const float* x_real = (const float*)d_in[0];
    const float* x_imag = (const float*)d_in[1];
    const float* dt     = (const float*)d_in[2];
    const float* nzr    = (const float*)d_in[3];
    const float* nzi    = (const float*)d_in[4];
    const float* ln_s_w = (const float*)d_in[5];
    const float* ln_s_b = (const float*)d_in[6];
    const float* conv_w = (const float*)d_in[7];
    const float* conv_b = (const float*)d_in[8];
    const float* ln_t_w = (const float*)d_in[9];
    const float* ln_t_b = (const float*)d_in[10];
    const float* lam_re = (const float*)d_in[11];
    const float* lam_im = (const float*)d_in[12];
    const float* sbr    = (const float*)d_in[13];
    const float* sbi    = (const float*)d_in[14];
    const float* enc_re = (const float*)d_in[15];
    const float* enc_im = (const float*)d_in[16];
    const float* dec_re = (const float*)d_in[17];
    const float* dec_im = (const float*)d_in[18];
    const float* rw     = (const float*)d_in[19];
    const float* rb     = (const float*)d_in[20];
    const float* w1     = (const float*)d_in[21];
    const float* b1     = (const float*)d_in[22];
    const float* w2     = (const float*)d_in[23];
    const float* b2     = (const float*)d_in[24];
    float* out = (float*)d_out;

    k0_tabs<<<8, 256>>>(lam_re, lam_im, dt);
    k1_ln_spatial<<<4096, 256>>>(x_real, x_imag, ln_s_w, ln_s_b);
    k2_conv<<<2048, 256>>>(conv_w, conv_b, x_real, x_imag);
    k3_lnt_enc<<<4096, 256>>>(ln_t_w, ln_t_b, enc_re, enc_im, sbr, sbi, dt, nzr, nzi);
    k4_scan_dec<<<2048, 256>>>(dec_re, dec_im);
    k5_moe<<<4096, 256>>>(rw, rb, w1, b1, w2, b2, out);
}

// round 12
// speedup vs baseline: 1.4365x; 1.0898x over previous
// UniPhyBlock fused pipeline. Round: restore exact R6 champion (2284us, f32x2
// everywhere; R6 k2 never spilled: ~150 regs < 255, so R8/R11 k2 variants were
// lateral/regressions). Changes vs R6:
//  1) dummy no-op launch before k2 shifts ncu's positional capture (launch #4)
//     from k3 -> k2, so next round finally profiles the conv kernel.
//  2) k5 gelu uses tanh.approx.f32 (1 MUFU op vs ~10-16 instr tanhf), cutting
//     issue pressure on 67M gelu evaluations. rel_err expected ~1e-4 (<1e-3).
#include <cuda_runtime.h>
#include <math.h>

#define Bc   2
#define Tc   16
#define Dc   64
#define Hc   64
#define Wc   64
#define C2   128
#define Ec   4
#define HIDc 128
#define NSc  0.01f
#define EPSc 1e-5f
#define HWc  4096
#define BTc  32
#define NPIX 131072
#define NBHW 8192
#define PLANE 8388608

typedef unsigned long long ull;

__device__ __forceinline__ ull pack2(float lo, float hi) {
    ull r;
    asm("mov.b64 %0, {%1, %2};" : "=l"(r) : "f"(lo), "f"(hi));
    return r;
}
__device__ __forceinline__ void unpack2(ull v, float& lo, float& hi) {
    asm("mov.b64 {%0, %1}, %2;" : "=f"(lo), "=f"(hi) : "l"(v));
}
#define FMA2(d, a, b, c) asm("fma.rn.f32x2 %0, %1, %2, %3;" : "=l"(d) : "l"(a), "l"(b), "l"(c))

__device__ __forceinline__ float tanh_fast(float x) {
    float y;
    asm("tanh.approx.f32 %0, %1;" : "=f"(y) : "f"(x));
    return y;
}

// ---------------- scratch (device globals; no allocation) ----------------
__device__ float g_xc[(size_t)NPIX * C2];
__device__ float g_s1r[PLANE];
__device__ float g_s1i[PLANE];
__device__ float g_ur[PLANE];
__device__ float g_ui[PLANE];
__device__ float g_drift[PLANE];
__device__ float g_ar[BTc * Dc];
__device__ float g_ai[BTc * Dc];
__device__ float g_fr[BTc * Dc];
__device__ float g_fi[BTc * Dc];

// dummy no-op: shifts which launch index ncu captures (positional -s)
__global__ void knop() {}

// ---------------- K0: per-(b,t,e) decay + forcing tables ----------------
__global__ void k0_tabs(const float* __restrict__ lam_re,
                        const float* __restrict__ lam_im,
                        const float* __restrict__ dt) {
    int idx = blockIdx.x * blockDim.x + threadIdx.x;
    if (idx >= BTc * Dc) return;
    int bt = idx / Dc, e = idx % Dc;
    float lr = lam_re[e];
    float sp = lr > 0.f ? lr + log1pf(expf(-lr)) : log1pf(expf(lr));
    float lre = -sp, lim = lam_im[e];
    float dtv = dt[bt];
    float er = expf(lre * dtv);
    float s, c;
    sincosf(lim * dtv, &s, &c);
    float ar = er * c, ai = er * s;
    float nr = ar - 1.f, ni = ai;
    float den = lre * lre + lim * lim;
    g_ar[idx] = ar; g_ai[idx] = ai;
    g_fr[idx] = (nr * lre + ni * lim) / den;
    g_fi[idx] = (ni * lre - nr * lim) / den;
}

// ---------------- K1: spatial complex LayerNorm -> NHWC concat ----------------
__global__ void __launch_bounds__(256) k1_ln_spatial(
        const float* __restrict__ xr, const float* __restrict__ xi,
        const float* __restrict__ lw, const float* __restrict__ lb) {
    __shared__ float sre[Dc][33], sim[Dc][33];
    __shared__ float smu[32], srs[32];
    int blk = blockIdx.x;
    int wt = blk & 1, h = (blk >> 1) & 63, bt = blk >> 7;
    int w0 = wt * 32;
    int tid = threadIdx.x;
    size_t base = ((size_t)bt * Dc) * HWc + h * Wc + w0;
    for (int lin = tid; lin < Dc * 32; lin += 256) {
        int d = lin >> 5, w = lin & 31;
        sre[d][w] = xr[base + (size_t)d * HWc + w];
        sim[d][w] = xi[base + (size_t)d * HWc + w];
    }
    __syncthreads();
    if (tid < 32) {
        float s = 0.f, sq = 0.f;
        for (int d = 0; d < Dc; d++) {
            float a = sre[d][tid], b = sim[d][tid];
            s += a + b; sq += a * a + b * b;
        }
        float mu = s * (1.f / 128.f);
        float var = sq * (1.f / 128.f) - mu * mu;
        smu[tid] = mu;
        srs[tid] = rsqrtf(var + EPSc);
    }
    __syncthreads();
    size_t obase = ((size_t)(bt * Hc + h) * Wc + w0) * C2;
    for (int lin = tid; lin < C2 * 32; lin += 256) {
        int w = lin >> 7, c = lin & 127;
        float v = (c < Dc) ? sre[c][w] : sim[c - Dc][w];
        v = (v - smu[w]) * srs[w] * lw[c] + lb[c];
        g_xc[obase + (size_t)w * C2 + c] = v;
    }
}

// ---------------- K2: 3x3 conv 128->128 + bias + resid (R6 champion form) ----------------
__global__ void __launch_bounds__(128) k2_conv(
        const float* __restrict__ cw, const float* __restrict__ cb,
        const float* __restrict__ xr, const float* __restrict__ xi) {
    __shared__ __align__(16) float sRow[34 * C2];
    int blk = blockIdx.x;
    int wt = blk & 1, h = (blk >> 1) & 63, bt = blk >> 7;
    int w0 = wt * 32;
    int o = threadIdx.x;
    ull acc[32];
    float bias = cb[o];
#pragma unroll
    for (int p = 0; p < 32; p++) acc[p] = pack2(bias, 0.f);

    for (int ky = 0; ky < 3; ky++) {
        int hh = h - 1 + ky;
        __syncthreads();
        for (int q = 0; q < 34; q++) {
            int ww = w0 - 1 + q;
            float v = 0.f;
            if (hh >= 0 && hh < Hc && ww >= 0 && ww < Wc)
                v = g_xc[((size_t)bt * HWc + hh * Wc + ww) * C2 + o];
            sRow[q * C2 + o] = v;
        }
        __syncthreads();
        const float* wbase = cw + (size_t)(ky * 3) * C2 * C2 + o;
        for (int ci = 0; ci < C2; ci += 2) {
            ull wA = pack2(wbase[ci * C2],               wbase[(ci + 1) * C2]);
            ull wB = pack2(wbase[C2 * C2 + ci * C2],     wbase[C2 * C2 + (ci + 1) * C2]);
            ull wC = pack2(wbase[2 * C2 * C2 + ci * C2], wbase[2 * C2 * C2 + (ci + 1) * C2]);
            ull v2[34];
#pragma unroll
            for (int q = 0; q < 34; q++)
                v2[q] = *reinterpret_cast<const ull*>(&sRow[q * C2 + ci]);
#pragma unroll
            for (int p = 0; p < 32; p++) {
                FMA2(acc[p], v2[p],     wA, acc[p]);
                FMA2(acc[p], v2[p + 1], wB, acc[p]);
                FMA2(acc[p], v2[p + 2], wC, acc[p]);
            }
        }
    }
    __syncthreads();
#pragma unroll
    for (int p = 0; p < 32; p++) {
        float lo, hi; unpack2(acc[p], lo, hi);
        sRow[o * 33 + p] = lo + hi;
    }
    __syncthreads();
    size_t pbase = ((size_t)bt * Dc) * HWc + h * Wc + w0;
    for (int lin = threadIdx.x; lin < C2 * 32; lin += 128) {
        int c = lin >> 5, p = lin & 31;
        float y = sRow[c * 33 + p];
        size_t addr = pbase + (size_t)(c & 63) * HWc + p;
        if (c < Dc) g_s1r[addr] = y + xr[addr];
        else        g_s1i[addr] = y + xi[addr];
    }
}

// ---------------- K3: temporal complex LN + encode (f32x2) ----------------
__global__ void __launch_bounds__(256) k3_lnt_enc(
        const float* __restrict__ lw, const float* __restrict__ lb,
        const float* __restrict__ er, const float* __restrict__ ei,
        const float* __restrict__ sbr, const float* __restrict__ sbi,
        const float* __restrict__ dt,
        const float* __restrict__ nzr, const float* __restrict__ nzi) {
    __shared__ __align__(16) float sre[Dc][36], sim[Dc][36];
    __shared__ float smu[32], srs[32];
    int blk = blockIdx.x;
    int wt = blk & 1, h = (blk >> 1) & 63, t = (blk >> 7) & 15, b = blk >> 11;
    int w0 = wt * 32;
    int tid = threadIdx.x;
    int bt = b * Tc + t;
    size_t base = ((size_t)bt * Dc) * HWc + h * Wc + w0;
    for (int lin = tid; lin < Dc * 32; lin += 256) {
        int d = lin >> 5, w = lin & 31;
        sre[d][w] = g_s1r[base + (size_t)d * HWc + w];
        sim[d][w] = g_s1i[base + (size_t)d * HWc + w];
    }
    __syncthreads();
    if (tid < 32) {
        float s = 0.f, sq = 0.f;
        for (int d = 0; d < Dc; d++) {
            float a = sre[d][tid], b2 = sim[d][tid];
            s += a + b2; sq += a * a + b2 * b2;
        }
        float mu = s * (1.f / 128.f);
        float var = sq * (1.f / 128.f) - mu * mu;
        smu[tid] = mu;
        srs[tid] = rsqrtf(var + EPSc);
    }
    __syncthreads();
    for (int lin = tid; lin < Dc * 32; lin += 256) {
        int d = lin >> 5, w = lin & 31;
        float m = smu[w], rs = srs[w];
        sre[d][w] = (sre[d][w] - m) * rs * lw[d] + lb[d];
        sim[d][w] = (sim[d][w] - m) * rs * lw[d + Dc] + lb[d + Dc];
    }
    __syncthreads();
    int e = tid & 63, g = tid >> 6;
    ull aR[4], aI[4];
#pragma unroll
    for (int k = 0; k < 4; k++) { aR[k] = 0ULL; aI[k] = 0ULL; }
    for (int d = 0; d < Dc; d++) {
        float eR = er[d * Dc + e], eI = ei[d * Dc + e];
        ull pR = pack2(eR, eR), pI = pack2(eI, eI), nI = pack2(-eI, -eI);
        const ull* xR = reinterpret_cast<const ull*>(&sre[d][g * 8]);
        const ull* xI = reinterpret_cast<const ull*>(&sim[d][g * 8]);
#pragma unroll
        for (int k = 0; k < 4; k++) {
            FMA2(aR[k], xR[k], pR, aR[k]);
            FMA2(aR[k], xI[k], nI, aR[k]);
            FMA2(aI[k], xR[k], pI, aI[k]);
            FMA2(aI[k], xI[k], pR, aI[k]);
        }
    }
    float dtv = dt[bt];
    float sq_dt = sqrtf(dtv) * NSc;
    float fR = g_fr[bt * Dc + e], fI = g_fi[bt * Dc + e];
    float bR = sbr[e], bI = sbi[e];
#pragma unroll
    for (int k = 0; k < 8; k++) {
        float aRk, aIk, tmp;
        if (k & 1) { unpack2(aR[k >> 1], tmp, aRk); unpack2(aI[k >> 1], tmp, aIk); }
        else       { unpack2(aR[k >> 1], aRk, tmp); unpack2(aI[k >> 1], aIk, tmp); }
        int w = g * 8 + k;
        size_t n = (size_t)b * HWc + h * Wc + w0 + w;
        size_t off = (n * Tc + t) * Dc + e;
        float uR = aRk + bR, uI = aIk + bI;
        float vR = uR * fR - uI * fI;
        float vI = uR * fI + uI * fR;
        vR += sq_dt * nzr[off];
        vI += sq_dt * nzi[off];
        g_ur[off] = vR;
        g_ui[off] = vI;
    }
}

// ---------------- K4: recurrence scan over T + decode (f32x2, ee-pairs) ----------------
__global__ void __launch_bounds__(256) k4_scan_dec(
        const float* __restrict__ dr_, const float* __restrict__ di_) {
    __shared__ __align__(16) float shR[4][16][64], shI[4][16][64];
    int blk = blockIdx.x;
    int n0 = blk * 4;
    int tid = threadIdx.x;
    int nn = tid >> 6, e = tid & 63;
    int n = n0 + nn;
    int b = n / HWc;
    float hR = 0.f, hI = 0.f;
    size_t ub = ((size_t)n * Tc) * Dc + e;
    for (int t = 0; t < Tc; t++) {
        int ti = (b * Tc + t) * Dc + e;
        float aRv = g_ar[ti], aIv = g_ai[ti];
        float uR = g_ur[ub + t * Dc], uI = g_ui[ub + t * Dc];
        float nR = aRv * hR - aIv * hI + uR;
        float nI = aRv * hI + aIv * hR + uI;
        hR = nR; hI = nI;
        shR[nn][t][e] = hR;
        shI[nn][t][e] = hI;
    }
    __syncthreads();
    int d = tid & 63, grp = tid >> 6;
    ull acc2[16];
#pragma unroll
    for (int t = 0; t < 16; t++) acc2[t] = 0ULL;
    for (int ee = 0; ee < Dc; ee += 2) {
        ull pR  = pack2(dr_[ee * Dc + d],  dr_[(ee + 1) * Dc + d]);
        ull pnI = pack2(-di_[ee * Dc + d], -di_[(ee + 1) * Dc + d]);
#pragma unroll
        for (int t = 0; t < 16; t++) {
            ull hr = *reinterpret_cast<const ull*>(&shR[grp][t][ee]);
            ull hi = *reinterpret_cast<const ull*>(&shI[grp][t][ee]);
            FMA2(acc2[t], hr, pR,  acc2[t]);
            FMA2(acc2[t], hi, pnI, acc2[t]);
        }
    }
    size_t ob = ((size_t)(n0 + grp) * Tc) * Dc + d;
#pragma unroll
    for (int t = 0; t < 16; t++) {
        float lo, hi; unpack2(acc2[t], lo, hi);
        g_drift[ob + t * Dc] = lo + hi;
    }
}

// ---------------- K5: MoE FFN (dense, f32x2 pixel-pairs, fast gelu) ----------------
__global__ void __launch_bounds__(256) k5_moe(
        const float* __restrict__ rw, const float* __restrict__ rb,
        const float* __restrict__ w1, const float* __restrict__ b1,
        const float* __restrict__ w2, const float* __restrict__ b2,
        float* __restrict__ out) {
    __shared__ __align__(16) float tokS[C2][36];
    __shared__ __align__(16) float hdnS[C2][36];
    __shared__ float gS[32][5];
    int blk = blockIdx.x;
    int wt = blk & 1, h = (blk >> 1) & 63, t = (blk >> 7) & 15, b = blk >> 11;
    int w0 = wt * 32;
    int tid = threadIdx.x;
    int bt = b * Tc + t;
    size_t base = ((size_t)bt * Dc) * HWc + h * Wc + w0;
    size_t nb = (size_t)b * HWc + h * Wc + w0;
    for (int lin = tid; lin < Dc * 32; lin += 256) {
        int w = lin >> 6, d = lin & 63;
        tokS[d][w] = g_drift[((nb + w) * Tc + t) * Dc + d];
    }
    __syncthreads();
    for (int lin = tid; lin < Dc * 32; lin += 256) {
        int d = lin >> 5, w = lin & 31;
        tokS[d][w] += g_s1r[base + (size_t)d * HWc + w];
        tokS[d + Dc][w] = g_s1i[base + (size_t)d * HWc + w];
    }
    __syncthreads();
    if (tid < 128) {
        int w = tid >> 2, e = tid & 3;
        float s = rb[e];
        for (int c = 0; c < C2; c++) s += tokS[c][w] * rw[c * Ec + e];
        gS[w][e] = s;
    }
    __syncthreads();
    if (tid < 32) {
        float m = fmaxf(fmaxf(gS[tid][0], gS[tid][1]), fmaxf(gS[tid][2], gS[tid][3]));
        float e0 = expf(gS[tid][0] - m), e1 = expf(gS[tid][1] - m);
        float e2 = expf(gS[tid][2] - m), e3 = expf(gS[tid][3] - m);
        float inv = 1.f / (e0 + e1 + e2 + e3);
        gS[tid][0] = e0 * inv; gS[tid][1] = e1 * inv;
        gS[tid][2] = e2 * inv; gS[tid][3] = e3 * inv;
    }
    __syncthreads();
    int col = tid & 127, hf = tid >> 7;
    ull outA[8];
#pragma unroll
    for (int k = 0; k < 8; k++) outA[k] = 0ULL;
    for (int ex = 0; ex < Ec; ex++) {
        ull acc[8];
        float bb = b1[ex * HIDc + col];
        ull bb2 = pack2(bb, bb);
#pragma unroll
        for (int k = 0; k < 8; k++) acc[k] = bb2;
        const float* w1p = w1 + (size_t)ex * C2 * HIDc + col;
        for (int d = 0; d < C2; d++) {
            float wv = w1p[d * HIDc];
            ull wp = pack2(wv, wv);
            const ull* vp = reinterpret_cast<const ull*>(&tokS[d][hf * 16]);
#pragma unroll
            for (int k = 0; k < 8; k++) FMA2(acc[k], vp[k], wp, acc[k]);
        }
        __syncthreads();
#pragma unroll
        for (int k = 0; k < 8; k++) {
            float x0, x1; unpack2(acc[k], x0, x1);
            x0 = 0.5f * x0 * (1.f + tanh_fast(0.7978845608028654f * (x0 + 0.044715f * x0 * x0 * x0)));
            x1 = 0.5f * x1 * (1.f + tanh_fast(0.7978845608028654f * (x1 + 0.044715f * x1 * x1 * x1)));
            hdnS[col][hf * 16 + 2 * k]     = x0;
            hdnS[col][hf * 16 + 2 * k + 1] = x1;
        }
        __syncthreads();
        ull acc2[8];
        float b2v = b2[ex * C2 + col];
        ull b2p = pack2(b2v, b2v);
#pragma unroll
        for (int k = 0; k < 8; k++) acc2[k] = b2p;
        const float* w2p = w2 + (size_t)ex * HIDc * C2 + col;
        for (int hh = 0; hh < HIDc; hh++) {
            float wv = w2p[hh * C2];
            ull wp = pack2(wv, wv);
            const ull* vp = reinterpret_cast<const ull*>(&hdnS[hh][hf * 16]);
#pragma unroll
            for (int k = 0; k < 8; k++) FMA2(acc2[k], vp[k], wp, acc2[k]);
        }
#pragma unroll
        for (int k = 0; k < 8; k++) {
            ull gp = pack2(gS[hf * 16 + 2 * k][ex], gS[hf * 16 + 2 * k + 1][ex]);
            FMA2(outA[k], acc2[k], gp, outA[k]);
        }
    }
    __syncthreads();
#pragma unroll
    for (int k = 0; k < 8; k++) {
        float lo, hi; unpack2(outA[k], lo, hi);
        hdnS[col][hf * 16 + 2 * k]     = lo;
        hdnS[col][hf * 16 + 2 * k + 1] = hi;
    }
    __syncthreads();
    for (int lin = tid; lin < C2 * 32; lin += 256) {
        int c = lin >> 5, p = lin & 31;
        float val = tokS[c][p] + hdnS[c][p];
        size_t addr = base + (size_t)(c & 63) * HWc + p;
        if (c >= Dc) addr += (size_t)PLANE;
        out[addr] = val;
    }
}

// ---------------- launch ----------------
extern "C" void kernel_launch(void* const* d_in, const int* in_sizes, int n_in,
                              void* d_out, int out_size) {
    (void)in_sizes; (void)n_in; (void)out_size;
    const float* x_real = (const float*)d_in[0];
    const float* x_imag = (const float*)d_in[1];
    const float* dt     = (const float*)d_in[2];
    const float* nzr    = (const float*)d_in[3];
    const float* nzi    = (const float*)d_in[4];
    const float* ln_s_w = (const float*)d_in[5];
    const float* ln_s_b = (const float*)d_in[6];
    const float* conv_w = (const float*)d_in[7];
    const float* conv_b = (const float*)d_in[8];
    const float* ln_t_w = (const float*)d_in[9];
    const float* ln_t_b = (const float*)d_in[10];
    const float* lam_re = (const float*)d_in[11];
    const float* lam_im = (const float*)d_in[12];
    const float* sbr    = (const float*)d_in[13];
    const float* sbi    = (const float*)d_in[14];
    const float* enc_re = (const float*)d_in[15];
    const float* enc_im = (const float*)d_in[16];
    const float* dec_re = (const float*)d_in[17];
    const float* dec_im = (const float*)d_in[18];
    const float* rw     = (const float*)d_in[19];
    const float* rb     = (const float*)d_in[20];
    const float* w1     = (const float*)d_in[21];
    const float* b1     = (const float*)d_in[22];
    const float* w2     = (const float*)d_in[23];
    const float* b2     = (const float*)d_in[24];
    float* out = (float*)d_out;

    k0_tabs<<<8, 256>>>(lam_re, lam_im, dt);
    k1_ln_spatial<<<4096, 256>>>(x_real, x_imag, ln_s_w, ln_s_b);
    knop<<<1, 32>>>();   // shifts ncu positional capture: launch #4 is now k2
    k2_conv<<<4096, 128>>>(conv_w, conv_b, x_real, x_imag);
    k3_lnt_enc<<<4096, 256>>>(ln_t_w, ln_t_b, enc_re, enc_im, sbr, sbi, dt, nzr, nzi);
    k4_scan_dec<<<2048, 256>>>(dec_re, dec_im);
    k5_moe<<<4096, 256>>>(rw, rb, w1, b1, w2, b2, out);
}